// round 3
// baseline (speedup 1.0000x reference)
#include <cuda_runtime.h>
#include <cstdint>

// out[b,p,d] = (sum_h hs[b,p,h] * W[prop[b,p], h, d] + bias[prop[b,p], d]) * mask[b,p]
// B=512, P=128 -> 65536 rows, H=512, D=2.
// One warp per row. hs row = 2KB contiguous, W row = 4KB contiguous (gathered, fits L2).
// NOTE: properties arrives as int32 (JAX x64 disabled downcasts the declared int64).

#define NROWS 65536
#define HDIM 512

__global__ __launch_bounds__(256) void adapter_kernel(
    const float* __restrict__ hs,          // [65536, 512]
    const int* __restrict__ props,         // [65536] int32
    const float* __restrict__ mask,        // [65536]
    const float* __restrict__ W,           // [10000, 512, 2]
    const float* __restrict__ bias,        // [10000, 2]
    float* __restrict__ out)               // [65536, 2]
{
    const int warp_in_blk = threadIdx.x >> 5;
    const int lane = threadIdx.x & 31;
    const int row = blockIdx.x * (blockDim.x >> 5) + warp_in_blk;
    if (row >= NROWS) return;

    const int p = props[row];

    const float4* __restrict__ h4 = reinterpret_cast<const float4*>(hs + (size_t)row * HDIM);
    const float4* __restrict__ w4 = reinterpret_cast<const float4*>(W + (size_t)p * (HDIM * 2));

    float acc0 = 0.f, acc1 = 0.f;

    // hs row: 128 float4 -> 4 per lane. W row: 256 float4 -> 8 per lane.
    // For hs float4 index k (h = 4k..4k+3), the matching W float4s are 2k and 2k+1
    // (each W float4 = two (d0,d1) pairs).
    #pragma unroll
    for (int i = 0; i < 4; i++) {
        const int k = i * 32 + lane;
        float4 h  = h4[k];
        float4 wa = w4[2 * k];       // h=4k:   (w00,w01), h=4k+1: (w10,w11)
        float4 wb = w4[2 * k + 1];   // h=4k+2, h=4k+3

        acc0 = fmaf(h.x, wa.x, acc0);
        acc1 = fmaf(h.x, wa.y, acc1);
        acc0 = fmaf(h.y, wa.z, acc0);
        acc1 = fmaf(h.y, wa.w, acc1);
        acc0 = fmaf(h.z, wb.x, acc0);
        acc1 = fmaf(h.z, wb.y, acc1);
        acc0 = fmaf(h.w, wb.z, acc0);
        acc1 = fmaf(h.w, wb.w, acc1);
    }

    // Warp tree reduction
    #pragma unroll
    for (int off = 16; off > 0; off >>= 1) {
        acc0 += __shfl_xor_sync(0xFFFFFFFFu, acc0, off);
        acc1 += __shfl_xor_sync(0xFFFFFFFFu, acc1, off);
    }

    if (lane == 0) {
        const float m = mask[row];
        const float b0 = bias[p * 2 + 0];
        const float b1 = bias[p * 2 + 1];
        float2 r;
        r.x = (acc0 + b0) * m;
        r.y = (acc1 + b1) * m;
        reinterpret_cast<float2*>(out)[row] = r;
    }
}

extern "C" void kernel_launch(void* const* d_in, const int* in_sizes, int n_in,
                              void* d_out, int out_size)
{
    const float* hs    = (const float*)d_in[0];
    const int*   props = (const int*)d_in[1];
    const float* mask  = (const float*)d_in[2];
    const float* W     = (const float*)d_in[3];
    const float* bias  = (const float*)d_in[4];
    float*       out   = (float*)d_out;

    // 8 warps per block, 1 row per warp
    const int threads = 256;
    const int rows_per_blk = threads / 32;
    const int blocks = (NROWS + rows_per_blk - 1) / rows_per_blk;
    adapter_kernel<<<blocks, threads>>>(hs, props, mask, W, bias, out);
}

// round 4
// speedup vs baseline: 1.1313x; 1.1313x over previous
#include <cuda_runtime.h>
#include <cstdint>

// out[b,p,d] = (sum_h hs[b,p,h] * W[prop[b,p], h, d] + bias[prop[b,p], d]) * mask[b,p]
// B=512, P=128 -> 65536 rows, H=512, D=2.
// One warp per row. hs row = 2KB contiguous (streamed, __ldcs so it never
// occupies L2), W row = 4KB contiguous gathered (41 MB table kept L2-resident).

#define NROWS 65536
#define HDIM 512

__global__ __launch_bounds__(256) void adapter_kernel(
    const float* __restrict__ hs,          // [65536, 512]
    const int* __restrict__ props,         // [65536] int32
    const float* __restrict__ mask,        // [65536]
    const float* __restrict__ W,           // [10000, 512, 2]
    const float* __restrict__ bias,        // [10000, 2]
    float* __restrict__ out)               // [65536, 2]
{
    const int warp_in_blk = threadIdx.x >> 5;
    const int lane = threadIdx.x & 31;
    const int row = blockIdx.x * (blockDim.x >> 5) + warp_in_blk;
    if (row >= NROWS) return;

    const int p = props[row];

    const float4* __restrict__ h4 = reinterpret_cast<const float4*>(hs + (size_t)row * HDIM);
    const float4* __restrict__ w4 = reinterpret_cast<const float4*>(W + (size_t)p * (HDIM * 2));

    float acc0 = 0.f, acc1 = 0.f;

    // hs row: 128 float4 -> 4 per lane (streaming loads, evict-first).
    // W row: 256 float4 -> 8 per lane (default caching, stays in L2).
    #pragma unroll
    for (int i = 0; i < 4; i++) {
        const int k = i * 32 + lane;
        float4 h  = __ldcs(&h4[k]);
        float4 wa = __ldg(&w4[2 * k]);       // h=4k:   (w00,w01), h=4k+1: (w10,w11)
        float4 wb = __ldg(&w4[2 * k + 1]);   // h=4k+2, h=4k+3

        acc0 = fmaf(h.x, wa.x, acc0);
        acc1 = fmaf(h.x, wa.y, acc1);
        acc0 = fmaf(h.y, wa.z, acc0);
        acc1 = fmaf(h.y, wa.w, acc1);
        acc0 = fmaf(h.z, wb.x, acc0);
        acc1 = fmaf(h.z, wb.y, acc1);
        acc0 = fmaf(h.w, wb.z, acc0);
        acc1 = fmaf(h.w, wb.w, acc1);
    }

    // Warp tree reduction
    #pragma unroll
    for (int off = 16; off > 0; off >>= 1) {
        acc0 += __shfl_xor_sync(0xFFFFFFFFu, acc0, off);
        acc1 += __shfl_xor_sync(0xFFFFFFFFu, acc1, off);
    }

    if (lane == 0) {
        const float m = mask[row];
        const float b0 = __ldg(&bias[p * 2 + 0]);
        const float b1 = __ldg(&bias[p * 2 + 1]);
        float2 r;
        r.x = (acc0 + b0) * m;
        r.y = (acc1 + b1) * m;
        __stcs(reinterpret_cast<float2*>(out) + row, r);
    }
}

extern "C" void kernel_launch(void* const* d_in, const int* in_sizes, int n_in,
                              void* d_out, int out_size)
{
    const float* hs    = (const float*)d_in[0];
    const int*   props = (const int*)d_in[1];
    const float* mask  = (const float*)d_in[2];
    const float* W     = (const float*)d_in[3];
    const float* bias  = (const float*)d_in[4];
    float*       out   = (float*)d_out;

    const int threads = 256;
    const int rows_per_blk = threads / 32;
    const int blocks = (NROWS + rows_per_blk - 1) / rows_per_blk;
    adapter_kernel<<<blocks, threads>>>(hs, props, mask, W, bias, out);
}